// round 5
// baseline (speedup 1.0000x reference)
#include <cuda_runtime.h>
#include <cstdint>

#define NTAG      48
#define START_TAG 46
#define STOP_TAG  47
#define BB        128
#define TT        256
#define RS        50                 // padded row stride (floats): conflict-free LDS
#define TILE_ELEMS (NTAG * RS)       // 2400
#define NBUF      8                  // deep cp.async pipeline (5 groups in flight)
#define NTHREADS  384                // 12 warps; j = tid>>3, s = tid&7

// dynamic smem layout (floats): tiles | P[2][48] | s_inv[2] | s_tgt[256] | s_red[384] | isLast
#define SMEM_FLOATS (NBUF * TILE_ELEMS + 96 + 2 + TT + NTHREADS + 4)
#define SMEM_BYTES  (SMEM_FLOATS * 4)

__device__ float        g_partials[BB];
__device__ unsigned int g_count = 0;

__device__ __forceinline__ void cp_async8(uint32_t dst, const void* src) {
    unsigned long long gsrc;
    asm volatile("cvta.to.global.u64 %0, %1;\n" : "=l"(gsrc) : "l"(src));
    asm volatile("cp.async.ca.shared.global [%0], [%1], 8;\n" :: "r"(dst), "l"(gsrc));
}
__device__ __forceinline__ void cp_commit() {
    asm volatile("cp.async.commit_group;\n" ::: "memory");
}
__device__ __forceinline__ void cp_wait_n(int n) {
    switch (n) {
        case 0: asm volatile("cp.async.wait_group 0;" ::: "memory"); break;
        case 1: asm volatile("cp.async.wait_group 1;" ::: "memory"); break;
        case 2: asm volatile("cp.async.wait_group 2;" ::: "memory"); break;
        case 3: asm volatile("cp.async.wait_group 3;" ::: "memory"); break;
        case 4: asm volatile("cp.async.wait_group 4;" ::: "memory"); break;
        case 5: asm volatile("cp.async.wait_group 5;" ::: "memory"); break;
        default: asm volatile("cp.async.wait_group 6;" ::: "memory"); break;
    }
}

// 48x48 f32 tile (192B rows) -> padded SMEM (200B stride). 3 x 8B per thread.
__device__ __forceinline__ void load_tile(uint32_t sbase, const float* g, int tid) {
    const int r0   = tid / 24;
    const int off8 = (tid % 24) * 8;
    #pragma unroll
    for (int it = 0; it < 3; ++it) {
        const int row = r0 + 16 * it;
        cp_async8(sbase + (uint32_t)(row * (RS * 4) + off8),
                  (const char*)g + row * (NTAG * 4) + off8);
    }
}

__device__ __forceinline__ void l2_prefetch_tile(const float* g, int tid) {
    const int r0   = tid / 24;
    const int off8 = (tid % 24) * 8;
    #pragma unroll
    for (int it = 0; it < 3; ++it) {
        const char* p = (const char*)g + (r0 + 16 * it) * (NTAG * 4) + off8;
        asm volatile("prefetch.global.L2 [%0];" :: "l"(p));
    }
}

// Convert raw tile to exp(tile) in place (2304 valid elems, 6 per thread);
// capture the raw gold value for target index tg before overwriting.
__device__ __forceinline__ void convert_tile(float* buf, int tg, float* goldAcc, int tid) {
    const int e0  = tid * 6;                 // never crosses a row (48 % 6 == 0)
    const int row = e0 / NTAG;
    float* bp = buf + row * RS + (e0 % NTAG);
    #pragma unroll
    for (int k = 0; k < 6; ++k) {
        const float v = bp[k];
        if (e0 + k == tg) *goldAcc += v;
        bp[k] = __expf(v);
    }
}

__global__ void __launch_bounds__(NTHREADS, 1) viterbi_fwd(
    const float* __restrict__ feats,
    const void* __restrict__ targets_raw,
    const void* __restrict__ lengths_raw,
    float* __restrict__ out)
{
    extern __shared__ __align__(16) float smem[];
    float* tiles   = smem;                          // NBUF * TILE_ELEMS
    float* P       = smem + NBUF * TILE_ELEMS;      // 2 * 48
    float* s_inv   = P + 96;                        // 2
    int*   s_tgt   = (int*)(s_inv + 2);             // 256
    float* s_red   = (float*)(s_tgt + TT);          // 384
    int*   s_isLast = (int*)(s_red + NTHREADS);

    const int b   = blockIdx.x;
    const int tid = threadIdx.x;

    // dtype probe: a genuine int64 length[0] lies in [1,256]; int32-misread >= 2^32.
    const long long probe = ((const long long*)lengths_raw)[0];
    const bool is64 = (probe >= 1 && probe <= TT);

    int len = is64 ? (int)((const long long*)lengths_raw)[b]
                   : ((const int*)lengths_raw)[b];
    if (len < 1)  len = 1;
    if (len > TT) len = TT;
    const float* fb = feats + (size_t)b * TT * (NTAG * NTAG);

    const uint32_t tbase0 = (uint32_t)__cvta_generic_to_shared(tiles);

    for (int c = tid; c < TT; c += NTHREADS) {
        int v = is64 ? (int)((const long long*)targets_raw)[(size_t)b * TT + c]
                     : ((const int*)targets_raw)[(size_t)b * TT + c];
        if (v < 0) v = 0;
        if (v >= NTAG * NTAG) v = NTAG * NTAG - 1;
        s_tgt[c] = v;
    }

    // Prologue: commit up to NBUF tile groups; L2-prefetch two beyond.
    const int npre = (len < NBUF) ? len : NBUF;
    for (int p = 0; p < npre; ++p) {
        load_tile(tbase0 + (uint32_t)(p * TILE_ELEMS * 4),
                  fb + (size_t)p * (NTAG * NTAG), tid);
        cp_commit();
    }
    if (NBUF     < len) l2_prefetch_tile(fb + (size_t)NBUF * (NTAG * NTAG), tid);
    if (NBUF + 1 < len) l2_prefetch_tile(fb + (size_t)(NBUF + 1) * (NTAG * NTAG), tid);
    // need tiles 0..min(2, len-1) resident before the first loop convert
    cp_wait_n(npre - ((len < 3) ? len : 3));
    __syncthreads();

    // init: P_0[j] = exp(features[b,0,START,j]); gold for t=0 from raw tile 0.
    float p0reg = 0.0f;
    if (tid < NTAG) {
        p0reg = __expf(tiles[START_TAG * RS + tid]);
        P[tid] = p0reg;
    }
    float goldAcc = 0.0f;
    float A = 0.0f;                       // meaningful on tid 0 only
    if (tid == 0) {
        const int tg = s_tgt[0];
        goldAcc = tiles[(tg / NTAG) * RS + (tg % NTAG)];
        s_inv[1] = 1.0f / p0reg;          // scale for step t=1
        if (len > 1) A = __logf(p0reg);
    }
    if (len > 1) convert_tile(tiles + TILE_ELEMS, s_tgt[1], &goldAcc, tid);
    __syncthreads();

    const int j = tid >> 3;               // destination tag
    const int s = tid & 7;                // source slice (6 each)
    int cur = 0;

    for (int t = 1; t < len; ++t) {
        const float* E   = tiles + (size_t)(t & (NBUF - 1)) * TILE_ELEMS;
        const float* Pc  = P + cur * NTAG;
        const float  inv = s_inv[t & 1];

        float acc0 = 0.0f, acc1 = 0.0f;
        #pragma unroll
        for (int k = 0; k < 3; ++k) {
            const int i = s * 6 + k;
            acc0 += E[i * RS + j] * Pc[i];
        }
        #pragma unroll
        for (int k = 3; k < 6; ++k) {
            const int i = s * 6 + k;
            acc1 += E[i * RS + j] * Pc[i];
        }
        float acc = (acc0 + acc1) * inv;
        acc += __shfl_xor_sync(0xffffffffu, acc, 1);
        acc += __shfl_xor_sync(0xffffffffu, acc, 2);
        acc += __shfl_xor_sync(0xffffffffu, acc, 4);

        if (s == 0) P[(cur ^ 1) * NTAG + j] = acc;
        if (tid == 0) {                   // j==0 group: acc == q_0
            s_inv[(t + 1) & 1] = __frcp_rn(acc);
            if (t < len - 1) A += __logf(acc);
        }

        // keep the pipe full: commit tile t+7, prefetch t+9
        if (t + NBUF - 1 < len) {
            load_tile(tbase0 + (uint32_t)(((t + NBUF - 1) & (NBUF - 1)) * TILE_ELEMS * 4),
                      fb + (size_t)(t + NBUF - 1) * (NTAG * NTAG), tid);
            cp_commit();
        }
        if (t + NBUF + 1 < len)
            l2_prefetch_tile(fb + (size_t)(t + NBUF + 1) * (NTAG * NTAG), tid);

        // convert tile t+1 (resident: waited at end of previous iteration)
        if (t + 1 < len)
            convert_tile(tiles + (size_t)((t + 1) & (NBUF - 1)) * TILE_ELEMS,
                         s_tgt[t + 1], &goldAcc, tid);

        // ensure tile t+2 resident for next iteration's convert; up to 5 groups stay in flight
        if (t + 2 < len) {
            int n = len - t - 3;
            if (n > NBUF - 3) n = NBUF - 3;
            cp_wait_n(n);
        }
        __syncthreads();
        cur ^= 1;
    }

    // gold reduction across 384 threads (fixed order, deterministic)
    s_red[tid] = goldAcc;
    __syncthreads();
    if (tid < 128) s_red[tid] += s_red[tid + 128] + s_red[tid + 256];
    __syncthreads();
    #pragma unroll
    for (int st = 64; st > 0; st >>= 1) {
        if (tid < st) s_red[tid] += s_red[tid + st];
        __syncthreads();
    }

    if (tid == 0) {
        const float val = (A + __logf(P[cur * NTAG + STOP_TAG])) - s_red[0];
        g_partials[b] = val;
        __threadfence();
        const unsigned done = atomicAdd(&g_count, 1);
        s_isLast[0] = (done == BB - 1) ? 1 : 0;
    }
    __syncthreads();

    // Last CTA reduces the 128 partials (fixed tree -> deterministic).
    if (s_isLast[0]) {
        if (tid < BB) s_red[tid] = g_partials[tid];
        __syncthreads();
        #pragma unroll
        for (int st = BB / 2; st > 0; st >>= 1) {
            if (tid < st) s_red[tid] += s_red[tid + st];
            __syncthreads();
        }
        if (tid == 0) {
            out[0] = s_red[0];
            g_count = 0;                  // reset for next graph replay
        }
    }
}

extern "C" void kernel_launch(void* const* d_in, const int* in_sizes, int n_in,
                              void* d_out, int out_size) {
    const float* feats   = nullptr;
    const void*  targets = nullptr;
    const void*  lengths = nullptr;
    for (int i = 0; i < n_in; ++i) {
        if (in_sizes[i] == BB * TT * NTAG * NTAG) feats   = (const float*)d_in[i];
        else if (in_sizes[i] == BB * TT)          targets = d_in[i];
        else if (in_sizes[i] == BB)               lengths = d_in[i];
    }
    cudaFuncSetAttribute(viterbi_fwd,
                         cudaFuncAttributeMaxDynamicSharedMemorySize, SMEM_BYTES);
    viterbi_fwd<<<BB, NTHREADS, SMEM_BYTES>>>(feats, targets, lengths, (float*)d_out);
}

// round 6
// speedup vs baseline: 1.4006x; 1.4006x over previous
#include <cuda_runtime.h>
#include <cstdint>

#define NTAG      48
#define START_TAG 46
#define STOP_TAG  47
#define BB        128
#define TT        256
#define RS        50                 // padded row stride: matvec LDS covers all 32 banks
#define TILE_ELEMS (NTAG * RS)       // 2400
#define NTHREADS  384                // 12 warps; j = tid>>3, s = tid&7

__device__ float        g_partials[BB];
__device__ unsigned int g_count = 0;

__device__ __forceinline__ float rcp_approx(float x) {
    float y;
    asm("rcp.approx.f32 %0, %1;" : "=f"(y) : "f"(x));
    return y;
}

__global__ void __launch_bounds__(NTHREADS, 1) viterbi_fwd(
    const float* __restrict__ feats,
    const void* __restrict__ targets_raw,
    const void* __restrict__ lengths_raw,
    float* __restrict__ out)
{
    __shared__ __align__(16) float tile[2][TILE_ELEMS];   // exp(feature) tiles
    __shared__ float P[2][NTAG];
    __shared__ float s_inv[2];
    __shared__ float s_q0[TT];
    __shared__ int   s_tgt[TT];
    __shared__ float s_red[NTHREADS];
    __shared__ int   s_isLast;

    const int b   = blockIdx.x;
    const int tid = threadIdx.x;

    // dtype probe: genuine int64 length[0] lies in [1,256]; int32-misread >= 2^32.
    const long long probe = ((const long long*)lengths_raw)[0];
    const bool is64 = (probe >= 1 && probe <= TT);

    int len = is64 ? (int)((const long long*)lengths_raw)[b]
                   : ((const int*)lengths_raw)[b];
    if (len < 1)  len = 1;
    if (len > TT) len = TT;
    const float* fb = feats + (size_t)b * TT * (NTAG * NTAG);

    for (int c = tid; c < TT; c += NTHREADS) {
        int v = is64 ? (int)((const long long*)targets_raw)[(size_t)b * TT + c]
                     : ((const int*)targets_raw)[(size_t)b * TT + c];
        if (v < 0) v = 0;
        if (v >= NTAG * NTAG) v = NTAG * NTAG - 1;
        s_tgt[c] = v;
    }

    // Per-thread element slice: 6 contiguous floats, never crossing a row.
    const int e0   = tid * 6;
    const int erow = e0 / NTAG;
    const int ecol = e0 % NTAG;
    float* stsA = &tile[0][erow * RS + ecol];
    float* stsB = &tile[1][erow * RS + ecol];

    float goldAcc = 0.0f;
    float r[2][6];                         // register tile buffers (parity = tile index & 1)

    // ---- prologue ----
    // LDG tile 1 -> r[1]
    if (len > 1) {
        const float2* g = (const float2*)(fb + 1 * (NTAG * NTAG) + e0);
        float2 a = g[0], c2 = g[1], d = g[2];
        r[1][0] = a.x;  r[1][1] = a.y;  r[1][2] = c2.x;
        r[1][3] = c2.y; r[1][4] = d.x;  r[1][5] = d.y;
    }
    // LDG tile 2 -> r[0]
    if (len > 2) {
        const float2* g = (const float2*)(fb + 2 * (NTAG * NTAG) + e0);
        float2 a = g[0], c2 = g[1], d = g[2];
        r[0][0] = a.x;  r[0][1] = a.y;  r[0][2] = c2.x;
        r[0][3] = c2.y; r[0][4] = d.x;  r[0][5] = d.y;
    }
    // P_0[j] = exp(features[b,0,START,j]) via direct LDG; gold t=0 on tid 0.
    if (tid < NTAG) {
        const float f = fb[START_TAG * NTAG + tid];
        const float p = __expf(f);
        P[0][tid] = p;
        if (tid == 0) {
            s_inv[1] = rcp_approx(p);
            s_q0[0]  = p;
        }
    }
    __syncthreads();   // s_tgt visible before gold checks below
    if (tid == 0) {
        const int tg = s_tgt[0];
        goldAcc += fb[tg];
    }
    // convert tile 1 regs -> smem tile[1]
    if (len > 1) {
        const int tg = s_tgt[1] - e0;      // in [0,5] if this thread owns it
        #pragma unroll
        for (int k = 0; k < 6; ++k) {
            const float v = r[1][k];
            if (k == tg) goldAcc += v;
            stsB[k] = __expf(v);
        }
    }
    __syncthreads();

    const int j = tid >> 3;                // destination tag
    const int s = tid & 7;                 // source slice (6 rows)
    const int co = (s * 6) * RS + j;       // matvec base offset into a tile

    #pragma unroll 2
    for (int t = 1; t < len; ++t) {
        // 1) issue LDG for tile t+2 (2-step distance hides DRAM latency)
        if (t + 2 < len) {
            const float2* g = (const float2*)(fb + (size_t)(t + 2) * (NTAG * NTAG) + e0);
            float2 a = g[0], c2 = g[1], d = g[2];
            r[t & 1][0] = a.x;  r[t & 1][1] = a.y;  r[t & 1][2] = c2.x;
            r[t & 1][3] = c2.y; r[t & 1][4] = d.x;  r[t & 1][5] = d.y;
        }

        // 2) matvec: q_j = inv * sum_i exp(feat)_{i,j} * P[i]
        const float* E   = &tile[t & 1][co];
        const float* Pc  = &P[(t + 1) & 1][s * 6];
        const float  inv = s_inv[t & 1];

        float acc0 = 0.0f, acc1 = 0.0f;
        #pragma unroll
        for (int k = 0; k < 3; ++k) acc0 += E[k * RS] * Pc[k];
        #pragma unroll
        for (int k = 3; k < 6; ++k) acc1 += E[k * RS] * Pc[k];
        float acc = (acc0 + acc1) * inv;
        acc += __shfl_xor_sync(0xffffffffu, acc, 1);
        acc += __shfl_xor_sync(0xffffffffu, acc, 2);
        acc += __shfl_xor_sync(0xffffffffu, acc, 4);

        if (s == 0) P[t & 1][j] = acc;
        if (tid == 0) {                    // j==0 group: acc == q_0
            s_inv[(t + 1) & 1] = rcp_approx(acc);
            s_q0[t] = acc;                 // logged in parallel at the end
        }

        // 3) convert tile t+1 (regs -> smem), gold check
        if (t + 1 < len) {
            float* sts = ((t + 1) & 1) ? stsB : stsA;
            const int tg = s_tgt[t + 1] - e0;
            #pragma unroll
            for (int k = 0; k < 6; ++k) {
                const float v = r[(t + 1) & 1][k];
                if (k == tg) goldAcc += v;
                sts[k] = __expf(v);
            }
        }
        __syncthreads();
    }

    // ---- epilogue: parallel logs + gold, fixed-order reduction ----
    float lg = 0.0f;
    if (tid < len - 1) lg = __logf(s_q0[tid]);
    s_red[tid] = lg - goldAcc;
    __syncthreads();
    if (tid < 128) s_red[tid] += s_red[tid + 128] + s_red[tid + 256];
    __syncthreads();
    #pragma unroll
    for (int st = 64; st > 0; st >>= 1) {
        if (tid < st) s_red[tid] += s_red[tid + st];
        __syncthreads();
    }

    if (tid == 0) {
        const float val = s_red[0] + __logf(P[(len - 1) & 1][STOP_TAG]);
        g_partials[b] = val;
        __threadfence();
        const unsigned done = atomicAdd(&g_count, 1);
        s_isLast = (done == BB - 1) ? 1 : 0;
    }
    __syncthreads();

    // Last CTA reduces the 128 partials (fixed tree -> deterministic).
    if (s_isLast) {
        if (tid < BB) s_red[tid] = g_partials[tid];
        __syncthreads();
        #pragma unroll
        for (int st = BB / 2; st > 0; st >>= 1) {
            if (tid < st) s_red[tid] += s_red[tid + st];
            __syncthreads();
        }
        if (tid == 0) {
            out[0] = s_red[0];
            g_count = 0;                   // reset for next graph replay
        }
    }
}

extern "C" void kernel_launch(void* const* d_in, const int* in_sizes, int n_in,
                              void* d_out, int out_size) {
    const float* feats   = nullptr;
    const void*  targets = nullptr;
    const void*  lengths = nullptr;
    for (int i = 0; i < n_in; ++i) {
        if (in_sizes[i] == BB * TT * NTAG * NTAG) feats   = (const float*)d_in[i];
        else if (in_sizes[i] == BB * TT)          targets = d_in[i];
        else if (in_sizes[i] == BB)               lengths = d_in[i];
    }
    viterbi_fwd<<<BB, NTHREADS>>>(feats, targets, lengths, (float*)d_out);
}